// round 10
// baseline (speedup 1.0000x reference)
#include <cuda_runtime.h>
#include <cuda_bf16.h>

#define BB 64
#define NN 128
#define FF 4
#define HH 100
#define HHP 104
#define NQ 25            // HH/4 d-quads
#define PP 8128          // NN*(NN-1)/2
#define THREADS 512

// Single fused kernel. Block = (batch, segment). 6 segments per batch:
//   seg: (J0, row_lo, rows)
//   0: j=0 J0=0   rows [0,32)
//   1: j=1 J0=32  rows [0,64)
//   2: j=2 J0=64  rows [0,64)
//   3: j=2 J0=64  rows [64,96)
//   4: j=3 J0=96  rows [0,64)
//   5: j=3 J0=96  rows [64,128)
__global__ void __launch_bounds__(THREADS, 2)
k_fused(const float* __restrict__ x,
        const float* __restrict__ W1, const float* __restrict__ b1,
        const float* __restrict__ W2, const float* __restrict__ b2,
        const float* __restrict__ W3, const float* __restrict__ b3p,
        float* __restrict__ out) {
    __shared__ __align__(16) float sA[64][HHP];     // A2 rows (c2 folded)
    __shared__ __align__(16) float4 sB4[NQ][32];    // B2 [dq][col]
    __shared__ __align__(16) float sM1[FF][HHP];
    __shared__ __align__(16) float sM2[FF][HHP];
    __shared__ __align__(16) float sc2[HHP];
    __shared__ __align__(16) float sW3[HHP];

    const int tid  = threadIdx.x;
    const int warp = tid >> 5;
    const int lane = tid & 31;

    const int b   = blockIdx.x / 6;
    const int seg = blockIdx.x % 6;
    const int J0     = (seg == 0) ? 0 : (seg == 1) ? 32 : (seg <= 3) ? 64 : 96;
    const int row_lo = (seg == 3 || seg == 5) ? 64 : 0;
    const int R      = (seg == 0) ? 32 : (seg == 3) ? 32 : 64;

    // ---- phase 0: stage W1/b1 into (aliased) sA scratch --------------------
    float* sAf  = &sA[0][0];
    float* sW1s = sAf;            // 800 floats
    float* sb1s = sAf + 800;      // 100 floats
    float* sPrt = sAf + 960;      // 200*9 = 1800 floats
    for (int i = tid; i < 2 * FF * HH; i += THREADS) sW1s[i] = W1[i];
    if (tid < HH) sb1s[tid] = b1[tid];
    __syncthreads();

    // ---- phase 1: fold M1 = W1[0:4]@W2, M2 = W1[4:8]@W2, c2 = b1@W2 + b2 ---
    if (tid < 200) {
        const int d  = tid % HH;
        const int k0 = (tid / HH) * 50;
        float m[9];
        #pragma unroll
        for (int i = 0; i < 9; ++i) m[i] = 0.f;
        #pragma unroll 5
        for (int kk = 0; kk < 50; ++kk) {
            int k = k0 + kk;
            float w = W2[k * HH + d];
            #pragma unroll
            for (int f = 0; f < FF; ++f) {
                m[f]     = fmaf(sW1s[f * HH + k],        w, m[f]);
                m[4 + f] = fmaf(sW1s[(FF + f) * HH + k], w, m[4 + f]);
            }
            m[8] = fmaf(sb1s[k], w, m[8]);
        }
        #pragma unroll
        for (int i = 0; i < 9; ++i) sPrt[tid * 9 + i] = m[i];
    }
    __syncthreads();
    if (tid < HH) {
        const int d = tid;
        float s[9];
        #pragma unroll
        for (int i = 0; i < 9; ++i) s[i] = sPrt[d * 9 + i] + sPrt[(HH + d) * 9 + i];
        #pragma unroll
        for (int f = 0; f < FF; ++f) { sM1[f][d] = s[f]; sM2[f][d] = s[4 + f]; }
        sc2[d] = s[8] + b2[d];
    } else if (tid >= 128 && tid < 128 + NQ) {
        int q = tid - 128;
        *(float4*)&sW3[q * 4] = ((const float4*)W3)[q];
    }
    __syncthreads();

    // ---- phase 2: node transforms into smem --------------------------------
    // A rows [row_lo, row_lo+R): a[d] = c2[d] + sum_f x[f]*M1[f][d]
    for (int it = tid; it < R * NQ; it += THREADS) {
        int dq  = it % NQ;
        int r   = it / NQ;
        int row = row_lo + r;
        int d0  = dq * 4;
        float4 xv = *(const float4*)(x + (b * NN + row) * FF);
        float4 a  = *(const float4*)&sc2[d0];
        #pragma unroll
        for (int f = 0; f < FF; ++f) {
            float xf = (f == 0) ? xv.x : (f == 1) ? xv.y : (f == 2) ? xv.z : xv.w;
            float4 m1 = *(const float4*)&sM1[f][d0];
            a.x = fmaf(xf, m1.x, a.x); a.y = fmaf(xf, m1.y, a.y);
            a.z = fmaf(xf, m1.z, a.z); a.w = fmaf(xf, m1.w, a.w);
        }
        *(float4*)&sA[r][d0] = a;
    }
    // B cols [J0, J0+32): v[d] = sum_f x[f]*M2[f][d]
    for (int it = tid; it < 32 * NQ; it += THREADS) {
        int col = it & 31;
        int dq  = it >> 5;
        int d0  = dq * 4;
        float4 xv = *(const float4*)(x + (b * NN + J0 + col) * FF);
        float4 v  = make_float4(0.f, 0.f, 0.f, 0.f);
        #pragma unroll
        for (int f = 0; f < FF; ++f) {
            float xf = (f == 0) ? xv.x : (f == 1) ? xv.y : (f == 2) ? xv.z : xv.w;
            float4 m2 = *(const float4*)&sM2[f][d0];
            v.x = fmaf(xf, m2.x, v.x); v.y = fmaf(xf, m2.y, v.y);
            v.z = fmaf(xf, m2.z, v.z); v.w = fmaf(xf, m2.w, v.w);
        }
        sB4[dq][col] = v;
    }
    __syncthreads();

    // ---- phase 3: pair tiles (2 i1-rows x 32 i2-lanes per warp) ------------
    const int i2 = J0 + lane;
    const float b3 = b3p[0];
    const int ntiles = R >> 1;

    for (int tix = warp; tix < ntiles; tix += 16) {
        const int r0 = tix * 2;
        const int I0 = row_lo + r0;
        float acc0 = 0.f, acc1 = 0.f;

        #pragma unroll 5
        for (int q = 0; q < NQ; ++q) {
            int d0 = q * 4;
            float4 a0 = *(const float4*)&sA[r0][d0];
            float4 a1 = *(const float4*)&sA[r0 + 1][d0];
            float4 w  = *(const float4*)&sW3[d0];
            float4 bq = sB4[q][lane];

            acc0 = fmaf(fmaxf(a0.x + bq.x, 0.f), w.x, acc0);
            acc1 = fmaf(fmaxf(a1.x + bq.x, 0.f), w.x, acc1);
            acc0 = fmaf(fmaxf(a0.y + bq.y, 0.f), w.y, acc0);
            acc1 = fmaf(fmaxf(a1.y + bq.y, 0.f), w.y, acc1);
            acc0 = fmaf(fmaxf(a0.z + bq.z, 0.f), w.z, acc0);
            acc1 = fmaf(fmaxf(a1.z + bq.z, 0.f), w.z, acc1);
            acc0 = fmaf(fmaxf(a0.w + bq.w, 0.f), w.w, acc0);
            acc1 = fmaf(fmaxf(a1.w + bq.w, 0.f), w.w, acc1);
        }

        int i1 = I0;
        if (i1 < i2) {
            float z = acc0 + b3;
            float s = 1.f / (1.f + __expf(-z));
            int p = i1 * (2 * NN - 1 - i1) / 2 + (i2 - i1 - 1);
            out[b * PP + p] = s;
        }
        i1 = I0 + 1;
        if (i1 < i2) {
            float z = acc1 + b3;
            float s = 1.f / (1.f + __expf(-z));
            int p = i1 * (2 * NN - 1 - i1) / 2 + (i2 - i1 - 1);
            out[b * PP + p] = s;
        }
    }
}

// ---------------------------------------------------------------- launch
extern "C" void kernel_launch(void* const* d_in, const int* in_sizes, int n_in,
                              void* d_out, int out_size) {
    const float* x  = (const float*)d_in[0];
    // d_in[1] = in_hitnr (unused by reference)
    const float* W1 = (const float*)d_in[2];
    const float* b1 = (const float*)d_in[3];
    const float* W2 = (const float*)d_in[4];
    const float* b2 = (const float*)d_in[5];
    const float* W3 = (const float*)d_in[6];
    const float* b3 = (const float*)d_in[7];
    float* out = (float*)d_out;

    k_fused<<<BB * 6, THREADS>>>(x, W1, b1, W2, b2, W3, b3, out);
}

// round 11
// speedup vs baseline: 1.0901x; 1.0901x over previous
#include <cuda_runtime.h>

#define BB 64
#define NN 128
#define FF 4
#define HH 100
#define HHP 104
#define NQ 25            // HH/4 quads
#define PP 8128          // NN*(NN-1)/2
#define THREADS 512

// dynamic smem layout (bytes)
#define OFF_A   0            // float sA[128][HHP]            = 53248
#define OFF_U   53248        // union: float4 sB4[2][NQ][32] (25600) | fold scratch
#define OFF_P   (OFF_U)          // float sPart[500][9]  = 18000
#define OFF_W1T (OFF_U + 18000)  // float sW1T[100][8]   = 3200
#define OFF_B1  (OFF_U + 21200)  // float sb1[100]       = 400
#define OFF_M1  78848        // float sM1[FF][HHP] = 1664
#define OFF_M2  80512        // float sM2[FF][HHP] = 1664
#define OFF_C2  82176        // float sc2[HHP]     = 416
#define OFF_W3  82592        // float sW3[HHP]     = 416
#define SMEM_TOTAL 83008

__device__ __forceinline__ int j_of(int g) { return (g < 8) ? 0 : (g < 24) ? 1 : (g < 48) ? 2 : 3; }
__device__ __forceinline__ int i0_of(int g, int j) {
    int base = (j == 0) ? 0 : (j == 1) ? 8 : (j == 2) ? 24 : 48;
    return (g - base) * 4;
}

// Single fused kernel. Block = (batch, seg). seg covers 16 consecutive tiles of
// the 80-tile list (j-major): one 4x32 pair tile per warp.
__global__ void __launch_bounds__(THREADS, 2)
k_fused(const float* __restrict__ x,
        const float* __restrict__ W1, const float* __restrict__ b1,
        const float* __restrict__ W2, const float* __restrict__ b2,
        const float* __restrict__ W3, const float* __restrict__ b3p,
        float* __restrict__ out) {
    extern __shared__ __align__(16) char smem[];
    float*  sA    = (float*)(smem + OFF_A);
    float4* sB4   = (float4*)(smem + OFF_U);
    float*  sPart = (float*)(smem + OFF_P);
    float*  sW1T  = (float*)(smem + OFF_W1T);
    float*  sb1   = (float*)(smem + OFF_B1);
    float*  sM1   = (float*)(smem + OFF_M1);
    float*  sM2   = (float*)(smem + OFF_M2);
    float*  sc2   = (float*)(smem + OFF_C2);
    float*  sW3   = (float*)(smem + OFF_W3);

    const int tid  = threadIdx.x;
    const int warp = tid >> 5;
    const int lane = tid & 31;
    const int b    = blockIdx.x / 5;
    const int seg  = blockIdx.x % 5;
    const int jlo  = j_of(seg * 16);
    const int jhi  = j_of(seg * 16 + 15);

    // ---- phase 0: stage W1 (transposed [k][8]), b1, W3 ---------------------
    for (int i = tid; i < 2 * FF * HH; i += THREADS) {
        int f = i / HH, k = i % HH;
        sW1T[k * 8 + f] = W1[i];
    }
    if (tid < HH) sb1[tid] = b1[tid];
    if (tid >= 128 && tid < 128 + NQ) {
        int q = tid - 128;
        *(float4*)(sW3 + q * 4) = ((const float4*)W3)[q];
    }
    __syncthreads();

    // ---- phase 1: fold partials. thread = (kc, d), 5 k-chunks of 20 --------
    if (tid < 500) {
        const int d  = tid % HH;
        const int kc = tid / HH;
        float m[9];
        #pragma unroll
        for (int i = 0; i < 9; ++i) m[i] = 0.f;
        #pragma unroll 5
        for (int kk = 0; kk < 20; ++kk) {
            int k = kc * 20 + kk;
            float w = W2[k * HH + d];                 // coalesced across d
            float4 wa = *(const float4*)(sW1T + k * 8);
            float4 wb = *(const float4*)(sW1T + k * 8 + 4);
            m[0] = fmaf(wa.x, w, m[0]); m[1] = fmaf(wa.y, w, m[1]);
            m[2] = fmaf(wa.z, w, m[2]); m[3] = fmaf(wa.w, w, m[3]);
            m[4] = fmaf(wb.x, w, m[4]); m[5] = fmaf(wb.y, w, m[5]);
            m[6] = fmaf(wb.z, w, m[6]); m[7] = fmaf(wb.w, w, m[7]);
            m[8] = fmaf(sb1[k], w, m[8]);
        }
        #pragma unroll
        for (int i = 0; i < 9; ++i) sPart[tid * 9 + i] = m[i];
    }
    __syncthreads();

    // ---- phase 1b: reduce 5 partials -> M1, M2, c2 -------------------------
    if (tid < HH) {
        float s[9];
        #pragma unroll
        for (int i = 0; i < 9; ++i) s[i] = 0.f;
        #pragma unroll
        for (int kc = 0; kc < 5; ++kc)
            #pragma unroll
            for (int i = 0; i < 9; ++i)
                s[i] += sPart[(kc * HH + tid) * 9 + i];
        #pragma unroll
        for (int f = 0; f < FF; ++f) { sM1[f * HHP + tid] = s[f]; sM2[f * HHP + tid] = s[4 + f]; }
        sc2[tid] = s[8] + b2[tid];
    }
    __syncthreads();

    // ---- phase 2a: A rows 0..127 (c2 folded) -------------------------------
    for (int it = tid; it < NN * NQ; it += THREADS) {
        int r = it / NQ, q = it % NQ, d0 = q * 4;
        float4 xv = *(const float4*)(x + (b * NN + r) * FF);
        float4 a  = *(const float4*)(sc2 + d0);
        #pragma unroll
        for (int f = 0; f < FF; ++f) {
            float xf = (f == 0) ? xv.x : (f == 1) ? xv.y : (f == 2) ? xv.z : xv.w;
            float4 m1 = *(const float4*)(sM1 + f * HHP + d0);
            a.x = fmaf(xf, m1.x, a.x); a.y = fmaf(xf, m1.y, a.y);
            a.z = fmaf(xf, m1.z, a.z); a.w = fmaf(xf, m1.w, a.w);
        }
        *(float4*)(sA + r * HHP + d0) = a;
    }
    // ---- phase 2b: B strips (2 slots; slot1 may duplicate slot0) -----------
    for (int it = tid; it < 2 * 32 * NQ; it += THREADS) {
        int s   = it / 800;
        int rem = it % 800;
        int q   = rem / 32;
        int col = rem % 32;
        int js  = (s == 0) ? jlo : jhi;
        int n   = js * 32 + col;
        int d0  = q * 4;
        float4 xv = *(const float4*)(x + (b * NN + n) * FF);
        float4 v  = make_float4(0.f, 0.f, 0.f, 0.f);
        #pragma unroll
        for (int f = 0; f < FF; ++f) {
            float xf = (f == 0) ? xv.x : (f == 1) ? xv.y : (f == 2) ? xv.z : xv.w;
            float4 m2 = *(const float4*)(sM2 + f * HHP + d0);
            v.x = fmaf(xf, m2.x, v.x); v.y = fmaf(xf, m2.y, v.y);
            v.z = fmaf(xf, m2.z, v.z); v.w = fmaf(xf, m2.w, v.w);
        }
        sB4[s * 800 + q * 32 + col] = v;
    }
    __syncthreads();

    // ---- phase 3: one 4x32 pair tile per warp ------------------------------
    const int g  = seg * 16 + warp;          // tile id in [0,80)
    const int j  = j_of(g);
    const int I0 = i0_of(g, j);
    const int jrel = j - jlo;                // 0 or 1
    const float4* Bp = sB4 + jrel * 800 + lane;
    const int i2 = j * 32 + lane;
    const float b3 = b3p[0];

    const float* A0 = sA + (I0 + 0) * HHP;
    const float* A1 = sA + (I0 + 1) * HHP;
    const float* A2r = sA + (I0 + 2) * HHP;
    const float* A3 = sA + (I0 + 3) * HHP;

    float acc0 = 0.f, acc1 = 0.f, acc2 = 0.f, acc3 = 0.f;
    #pragma unroll 5
    for (int q = 0; q < NQ; ++q) {
        int d0 = q * 4;
        float4 a0 = *(const float4*)(A0 + d0);
        float4 a1 = *(const float4*)(A1 + d0);
        float4 a2 = *(const float4*)(A2r + d0);
        float4 a3 = *(const float4*)(A3 + d0);
        float4 w  = *(const float4*)(sW3 + d0);
        float4 bq = Bp[q * 32];

        acc0 = fmaf(fmaxf(a0.x + bq.x, 0.f), w.x, acc0);
        acc1 = fmaf(fmaxf(a1.x + bq.x, 0.f), w.x, acc1);
        acc2 = fmaf(fmaxf(a2.x + bq.x, 0.f), w.x, acc2);
        acc3 = fmaf(fmaxf(a3.x + bq.x, 0.f), w.x, acc3);

        acc0 = fmaf(fmaxf(a0.y + bq.y, 0.f), w.y, acc0);
        acc1 = fmaf(fmaxf(a1.y + bq.y, 0.f), w.y, acc1);
        acc2 = fmaf(fmaxf(a2.y + bq.y, 0.f), w.y, acc2);
        acc3 = fmaf(fmaxf(a3.y + bq.y, 0.f), w.y, acc3);

        acc0 = fmaf(fmaxf(a0.z + bq.z, 0.f), w.z, acc0);
        acc1 = fmaf(fmaxf(a1.z + bq.z, 0.f), w.z, acc1);
        acc2 = fmaf(fmaxf(a2.z + bq.z, 0.f), w.z, acc2);
        acc3 = fmaf(fmaxf(a3.z + bq.z, 0.f), w.z, acc3);

        acc0 = fmaf(fmaxf(a0.w + bq.w, 0.f), w.w, acc0);
        acc1 = fmaf(fmaxf(a1.w + bq.w, 0.f), w.w, acc1);
        acc2 = fmaf(fmaxf(a2.w + bq.w, 0.f), w.w, acc2);
        acc3 = fmaf(fmaxf(a3.w + bq.w, 0.f), w.w, acc3);
    }

    float accs[4] = {acc0, acc1, acc2, acc3};
    #pragma unroll
    for (int t = 0; t < 4; ++t) {
        int i1 = I0 + t;
        if (i1 < i2) {
            float z = accs[t] + b3;
            float s = 1.f / (1.f + __expf(-z));
            int p = i1 * (2 * NN - 1 - i1) / 2 + (i2 - i1 - 1);
            out[b * PP + p] = s;
        }
    }
}

// ---------------------------------------------------------------- launch
extern "C" void kernel_launch(void* const* d_in, const int* in_sizes, int n_in,
                              void* d_out, int out_size) {
    const float* x  = (const float*)d_in[0];
    // d_in[1] = in_hitnr (unused by reference)
    const float* W1 = (const float*)d_in[2];
    const float* b1 = (const float*)d_in[3];
    const float* W2 = (const float*)d_in[4];
    const float* b2 = (const float*)d_in[5];
    const float* W3 = (const float*)d_in[6];
    const float* b3 = (const float*)d_in[7];
    float* out = (float*)d_out;

    cudaFuncSetAttribute(k_fused, cudaFuncAttributeMaxDynamicSharedMemorySize, SMEM_TOTAL);
    k_fused<<<BB * 5, THREADS, SMEM_TOTAL>>>(x, W1, b1, W2, b2, W3, b3, out);
}

// round 12
// speedup vs baseline: 1.3611x; 1.2486x over previous
#include <cuda_runtime.h>

#define BB 64
#define NN 128
#define FF 4
#define HH 100
#define HHP 104
#define NQ 25            // HH/4 quads
#define PP 8128          // NN*(NN-1)/2

// folded weights (written by k_fold, read by k_pairs)
__device__ __align__(16) float g_M1[FF * HHP];
__device__ __align__(16) float g_M2[FF * HHP];
__device__ __align__(16) float g_c2[HHP];

// ---------------------------------------------------------------- K1: fold (one block)
__global__ void __launch_bounds__(512) k_fold(const float* __restrict__ W1,
                                              const float* __restrict__ b1,
                                              const float* __restrict__ W2,
                                              const float* __restrict__ b2) {
    __shared__ float sW1T[HH * 8];        // [k][f] transposed
    __shared__ float sb1[HH];
    __shared__ float sPart[500 * 9];
    const int tid = threadIdx.x;

    for (int i = tid; i < 2 * FF * HH; i += 512) {
        int f = i / HH, k = i % HH;
        sW1T[k * 8 + f] = W1[i];
    }
    if (tid < HH) sb1[tid] = b1[tid];
    __syncthreads();

    if (tid < 500) {
        const int d  = tid % HH;
        const int kc = tid / HH;
        float m[9];
        #pragma unroll
        for (int i = 0; i < 9; ++i) m[i] = 0.f;
        #pragma unroll 5
        for (int kk = 0; kk < 20; ++kk) {
            int k = kc * 20 + kk;
            float w = W2[k * HH + d];
            float4 wa = *(const float4*)(sW1T + k * 8);
            float4 wb = *(const float4*)(sW1T + k * 8 + 4);
            m[0] = fmaf(wa.x, w, m[0]); m[1] = fmaf(wa.y, w, m[1]);
            m[2] = fmaf(wa.z, w, m[2]); m[3] = fmaf(wa.w, w, m[3]);
            m[4] = fmaf(wb.x, w, m[4]); m[5] = fmaf(wb.y, w, m[5]);
            m[6] = fmaf(wb.z, w, m[6]); m[7] = fmaf(wb.w, w, m[7]);
            m[8] = fmaf(sb1[k], w, m[8]);
        }
        #pragma unroll
        for (int i = 0; i < 9; ++i) sPart[tid * 9 + i] = m[i];
    }
    __syncthreads();

    if (tid < HH) {
        float s[9];
        #pragma unroll
        for (int i = 0; i < 9; ++i) s[i] = 0.f;
        #pragma unroll
        for (int kc = 0; kc < 5; ++kc)
            #pragma unroll
            for (int i = 0; i < 9; ++i)
                s[i] += sPart[(kc * HH + tid) * 9 + i];
        #pragma unroll
        for (int f = 0; f < FF; ++f) { g_M1[f * HHP + tid] = s[f]; g_M2[f * HHP + tid] = s[4 + f]; }
        g_c2[tid] = s[8] + b2[tid];
    }
}

// ---------------------------------------------------------------- K2: fused transform + pairs
// Block = (batch, seg). 10 segments of 8 tiles; each seg = one 32-col strip (J0)
// x 32 consecutive A-rows (row_lo). Warp w handles the 4x32 tile at rows
// row_lo + 4w.
__global__ void __launch_bounds__(256, 5)
k_pairs(const float* __restrict__ x,
        const float* __restrict__ W3, const float* __restrict__ b3p,
        float* __restrict__ out) {
    __shared__ __align__(16) float  sA[32 * HHP];      // 13312 B
    __shared__ __align__(16) float4 sB4[NQ * 32];      // 12800 B
    __shared__ __align__(16) float  sM1[FF * HHP];
    __shared__ __align__(16) float  sM2[FF * HHP];
    __shared__ __align__(16) float  sc2[HHP];
    __shared__ __align__(16) float  sW3[HHP];

    const int tid  = threadIdx.x;
    const int warp = tid >> 5;
    const int lane = tid & 31;
    const int b    = blockIdx.x / 10;
    const int seg  = blockIdx.x % 10;

    // seg -> (J0, row_lo):  {0,32,32,64,64,64,96,96,96,96} / {0,0,32,0,32,64,0,32,64,96}
    const int j      = (seg == 0) ? 0 : (seg <= 2) ? 1 : (seg <= 5) ? 2 : 3;
    const int J0     = j * 32;
    const int base   = (j == 0) ? 0 : (j == 1) ? 1 : (j == 2) ? 3 : 6;
    const int row_lo = (seg - base) * 32;

    // ---- phase 0: stage folded weights + W3 --------------------------------
    for (int i = tid; i < FF * HHP / 4; i += 256) {
        ((float4*)sM1)[i] = ((const float4*)g_M1)[i];
        ((float4*)sM2)[i] = ((const float4*)g_M2)[i];
    }
    if (tid < HHP / 4) ((float4*)sc2)[tid] = ((const float4*)g_c2)[tid];
    else if (tid >= 32 && tid < 32 + NQ) {
        int q = tid - 32;
        *(float4*)(sW3 + q * 4) = ((const float4*)W3)[q];
    }
    __syncthreads();

    // ---- phase 1a: A rows [row_lo, row_lo+32), c2 folded in ----------------
    for (int it = tid; it < 32 * NQ; it += 256) {
        int r = it / NQ, q = it % NQ, d0 = q * 4;
        float4 xv = *(const float4*)(x + (b * NN + row_lo + r) * FF);
        float4 a  = *(const float4*)(sc2 + d0);
        #pragma unroll
        for (int f = 0; f < FF; ++f) {
            float xf = (f == 0) ? xv.x : (f == 1) ? xv.y : (f == 2) ? xv.z : xv.w;
            float4 m1 = *(const float4*)(sM1 + f * HHP + d0);
            a.x = fmaf(xf, m1.x, a.x); a.y = fmaf(xf, m1.y, a.y);
            a.z = fmaf(xf, m1.z, a.z); a.w = fmaf(xf, m1.w, a.w);
        }
        *(float4*)(sA + r * HHP + d0) = a;
    }
    // ---- phase 1b: B strip cols [J0, J0+32) --------------------------------
    for (int it = tid; it < 32 * NQ; it += 256) {
        int col = it & 31, q = it >> 5, d0 = q * 4;
        float4 xv = *(const float4*)(x + (b * NN + J0 + col) * FF);
        float4 v  = make_float4(0.f, 0.f, 0.f, 0.f);
        #pragma unroll
        for (int f = 0; f < FF; ++f) {
            float xf = (f == 0) ? xv.x : (f == 1) ? xv.y : (f == 2) ? xv.z : xv.w;
            float4 m2 = *(const float4*)(sM2 + f * HHP + d0);
            v.x = fmaf(xf, m2.x, v.x); v.y = fmaf(xf, m2.y, v.y);
            v.z = fmaf(xf, m2.z, v.z); v.w = fmaf(xf, m2.w, v.w);
        }
        sB4[q * 32 + col] = v;
    }
    __syncthreads();

    // ---- phase 2: one 4x32 tile per warp -----------------------------------
    const int r0 = warp * 4;               // local row of tile
    const int I0 = row_lo + r0;
    const int i2 = J0 + lane;
    const float b3 = b3p[0];

    const float* A0 = sA + (r0 + 0) * HHP;
    const float* A1 = sA + (r0 + 1) * HHP;
    const float* A2 = sA + (r0 + 2) * HHP;
    const float* A3 = sA + (r0 + 3) * HHP;
    const float4* Bp = sB4 + lane;

    float acc0 = 0.f, acc1 = 0.f, acc2 = 0.f, acc3 = 0.f;
    #pragma unroll 5
    for (int q = 0; q < NQ; ++q) {
        int d0 = q * 4;
        float4 a0 = *(const float4*)(A0 + d0);
        float4 a1 = *(const float4*)(A1 + d0);
        float4 a2 = *(const float4*)(A2 + d0);
        float4 a3 = *(const float4*)(A3 + d0);
        float4 w  = *(const float4*)(sW3 + d0);
        float4 bq = Bp[q * 32];

        acc0 = fmaf(fmaxf(a0.x + bq.x, 0.f), w.x, acc0);
        acc1 = fmaf(fmaxf(a1.x + bq.x, 0.f), w.x, acc1);
        acc2 = fmaf(fmaxf(a2.x + bq.x, 0.f), w.x, acc2);
        acc3 = fmaf(fmaxf(a3.x + bq.x, 0.f), w.x, acc3);

        acc0 = fmaf(fmaxf(a0.y + bq.y, 0.f), w.y, acc0);
        acc1 = fmaf(fmaxf(a1.y + bq.y, 0.f), w.y, acc1);
        acc2 = fmaf(fmaxf(a2.y + bq.y, 0.f), w.y, acc2);
        acc3 = fmaf(fmaxf(a3.y + bq.y, 0.f), w.y, acc3);

        acc0 = fmaf(fmaxf(a0.z + bq.z, 0.f), w.z, acc0);
        acc1 = fmaf(fmaxf(a1.z + bq.z, 0.f), w.z, acc1);
        acc2 = fmaf(fmaxf(a2.z + bq.z, 0.f), w.z, acc2);
        acc3 = fmaf(fmaxf(a3.z + bq.z, 0.f), w.z, acc3);

        acc0 = fmaf(fmaxf(a0.w + bq.w, 0.f), w.w, acc0);
        acc1 = fmaf(fmaxf(a1.w + bq.w, 0.f), w.w, acc1);
        acc2 = fmaf(fmaxf(a2.w + bq.w, 0.f), w.w, acc2);
        acc3 = fmaf(fmaxf(a3.w + bq.w, 0.f), w.w, acc3);
    }

    float accs[4] = {acc0, acc1, acc2, acc3};
    #pragma unroll
    for (int t = 0; t < 4; ++t) {
        int i1 = I0 + t;
        if (i1 < i2) {
            float z = accs[t] + b3;
            float s = 1.f / (1.f + __expf(-z));
            int p = i1 * (2 * NN - 1 - i1) / 2 + (i2 - i1 - 1);
            out[b * PP + p] = s;
        }
    }
}

// ---------------------------------------------------------------- launch
extern "C" void kernel_launch(void* const* d_in, const int* in_sizes, int n_in,
                              void* d_out, int out_size) {
    const float* x  = (const float*)d_in[0];
    // d_in[1] = in_hitnr (unused by reference)
    const float* W1 = (const float*)d_in[2];
    const float* b1 = (const float*)d_in[3];
    const float* W2 = (const float*)d_in[4];
    const float* b2 = (const float*)d_in[5];
    const float* W3 = (const float*)d_in[6];
    const float* b3 = (const float*)d_in[7];
    float* out = (float*)d_out;

    k_fold<<<1, 512>>>(W1, b1, W2, b2);
    k_pairs<<<BB * 10, 256>>>(x, W3, b3, out);
}

// round 13
// speedup vs baseline: 1.4781x; 1.0860x over previous
#include <cuda_runtime.h>

#define BB 64
#define NN 128
#define FF 4
#define HH 100
#define HHP 104
#define NQ 25            // HH/4 quads
#define PP 8128          // NN*(NN-1)/2

typedef unsigned long long u64;

// folded weights (written by k_fold, read by k_pairs)
__device__ __align__(16) float g_M1[FF * HHP];
__device__ __align__(16) float g_M2[FF * HHP];
__device__ __align__(16) float g_c2[HHP];

// packed 2-dim pair op: acc += max(a+b, 0) * w   (both f32 halves)
// Single asm block so ptxas allocates {lo,hi} as the pair halves (no MOVs):
// expected SASS = FADD2, FMNMX, FMNMX, FFMA2.
__device__ __forceinline__ void pd2(u64 a, u64 b, u64 w, u64& acc) {
    asm("{\n\t"
        ".reg .b64 t;\n\t"
        ".reg .f32 lo, hi;\n\t"
        "add.rn.f32x2 t, %1, %2;\n\t"
        "mov.b64 {lo, hi}, t;\n\t"
        "max.f32 lo, lo, 0f00000000;\n\t"
        "max.f32 hi, hi, 0f00000000;\n\t"
        "mov.b64 t, {lo, hi};\n\t"
        "fma.rn.f32x2 %0, t, %3, %0;\n\t"
        "}" : "+l"(acc) : "l"(a), "l"(b), "l"(w));
}

__device__ __forceinline__ float2 unpk(u64 t) {
    float2 f;
    asm("mov.b64 {%0, %1}, %2;" : "=f"(f.x), "=f"(f.y) : "l"(t));
    return f;
}

// ---------------------------------------------------------------- K1: fold (one block)
__global__ void __launch_bounds__(512) k_fold(const float* __restrict__ W1,
                                              const float* __restrict__ b1,
                                              const float* __restrict__ W2,
                                              const float* __restrict__ b2) {
    __shared__ float sW1T[HH * 8];        // [k][f] transposed
    __shared__ float sb1[HH];
    __shared__ float sPart[500 * 9];
    const int tid = threadIdx.x;

    for (int i = tid; i < 2 * FF * HH; i += 512) {
        int f = i / HH, k = i % HH;
        sW1T[k * 8 + f] = W1[i];
    }
    if (tid < HH) sb1[tid] = b1[tid];
    __syncthreads();

    if (tid < 500) {
        const int d  = tid % HH;
        const int kc = tid / HH;
        float m[9];
        #pragma unroll
        for (int i = 0; i < 9; ++i) m[i] = 0.f;
        #pragma unroll 5
        for (int kk = 0; kk < 20; ++kk) {
            int k = kc * 20 + kk;
            float w = W2[k * HH + d];
            float4 wa = *(const float4*)(sW1T + k * 8);
            float4 wb = *(const float4*)(sW1T + k * 8 + 4);
            m[0] = fmaf(wa.x, w, m[0]); m[1] = fmaf(wa.y, w, m[1]);
            m[2] = fmaf(wa.z, w, m[2]); m[3] = fmaf(wa.w, w, m[3]);
            m[4] = fmaf(wb.x, w, m[4]); m[5] = fmaf(wb.y, w, m[5]);
            m[6] = fmaf(wb.z, w, m[6]); m[7] = fmaf(wb.w, w, m[7]);
            m[8] = fmaf(sb1[k], w, m[8]);
        }
        #pragma unroll
        for (int i = 0; i < 9; ++i) sPart[tid * 9 + i] = m[i];
    }
    __syncthreads();

    if (tid < HH) {
        float s[9];
        #pragma unroll
        for (int i = 0; i < 9; ++i) s[i] = 0.f;
        #pragma unroll
        for (int kc = 0; kc < 5; ++kc)
            #pragma unroll
            for (int i = 0; i < 9; ++i)
                s[i] += sPart[(kc * HH + tid) * 9 + i];
        #pragma unroll
        for (int f = 0; f < FF; ++f) { g_M1[f * HHP + tid] = s[f]; g_M2[f * HHP + tid] = s[4 + f]; }
        g_c2[tid] = s[8] + b2[tid];
    }
}

// ---------------------------------------------------------------- K2: fused transform + pairs
// Block = (batch, seg). 10 segments of 8 tiles; each seg = one 32-col strip (J0)
// x 32 consecutive A-rows (row_lo). Warp w handles the 4x32 tile at rows
// row_lo + 4w. Inner math in packed f32x2.
__global__ void __launch_bounds__(256, 5)
k_pairs(const float* __restrict__ x,
        const float* __restrict__ W3, const float* __restrict__ b3p,
        float* __restrict__ out) {
    __shared__ __align__(16) float  sA[32 * HHP];      // 13312 B
    __shared__ __align__(16) float4 sB4[NQ * 32];      // 12800 B
    __shared__ __align__(16) float  sM1[FF * HHP];
    __shared__ __align__(16) float  sM2[FF * HHP];
    __shared__ __align__(16) float  sc2[HHP];
    __shared__ __align__(16) float  sW3[HHP];

    const int tid  = threadIdx.x;
    const int warp = tid >> 5;
    const int lane = tid & 31;
    const int b    = blockIdx.x / 10;
    const int seg  = blockIdx.x % 10;

    // seg -> (J0, row_lo):  j = {0,1,1,2,2,2,3,3,3,3}
    const int j      = (seg == 0) ? 0 : (seg <= 2) ? 1 : (seg <= 5) ? 2 : 3;
    const int J0     = j * 32;
    const int base   = (j == 0) ? 0 : (j == 1) ? 1 : (j == 2) ? 3 : 6;
    const int row_lo = (seg - base) * 32;

    // ---- phase 0: stage folded weights + W3 --------------------------------
    for (int i = tid; i < FF * HHP / 4; i += 256) {
        ((float4*)sM1)[i] = ((const float4*)g_M1)[i];
        ((float4*)sM2)[i] = ((const float4*)g_M2)[i];
    }
    if (tid < HHP / 4) ((float4*)sc2)[tid] = ((const float4*)g_c2)[tid];
    else if (tid >= 32 && tid < 32 + NQ) {
        int q = tid - 32;
        *(float4*)(sW3 + q * 4) = ((const float4*)W3)[q];
    }
    __syncthreads();

    // ---- phase 1a: A rows [row_lo, row_lo+32), c2 folded in ----------------
    for (int it = tid; it < 32 * NQ; it += 256) {
        int r = it / NQ, q = it % NQ, d0 = q * 4;
        float4 xv = *(const float4*)(x + (b * NN + row_lo + r) * FF);
        float4 a  = *(const float4*)(sc2 + d0);
        #pragma unroll
        for (int f = 0; f < FF; ++f) {
            float xf = (f == 0) ? xv.x : (f == 1) ? xv.y : (f == 2) ? xv.z : xv.w;
            float4 m1 = *(const float4*)(sM1 + f * HHP + d0);
            a.x = fmaf(xf, m1.x, a.x); a.y = fmaf(xf, m1.y, a.y);
            a.z = fmaf(xf, m1.z, a.z); a.w = fmaf(xf, m1.w, a.w);
        }
        *(float4*)(sA + r * HHP + d0) = a;
    }
    // ---- phase 1b: B strip cols [J0, J0+32) --------------------------------
    for (int it = tid; it < 32 * NQ; it += 256) {
        int col = it & 31, q = it >> 5, d0 = q * 4;
        float4 xv = *(const float4*)(x + (b * NN + J0 + col) * FF);
        float4 v  = make_float4(0.f, 0.f, 0.f, 0.f);
        #pragma unroll
        for (int f = 0; f < FF; ++f) {
            float xf = (f == 0) ? xv.x : (f == 1) ? xv.y : (f == 2) ? xv.z : xv.w;
            float4 m2 = *(const float4*)(sM2 + f * HHP + d0);
            v.x = fmaf(xf, m2.x, v.x); v.y = fmaf(xf, m2.y, v.y);
            v.z = fmaf(xf, m2.z, v.z); v.w = fmaf(xf, m2.w, v.w);
        }
        sB4[q * 32 + col] = v;
    }
    __syncthreads();

    // ---- phase 2: one 4x32 tile per warp, packed f32x2 math ----------------
    const int r0 = warp * 4;               // local row of tile
    const int I0 = row_lo + r0;
    const int i2 = J0 + lane;
    const float b3 = b3p[0];

    const ulonglong2* A0 = (const ulonglong2*)(sA + (r0 + 0) * HHP);
    const ulonglong2* A1 = (const ulonglong2*)(sA + (r0 + 1) * HHP);
    const ulonglong2* A2 = (const ulonglong2*)(sA + (r0 + 2) * HHP);
    const ulonglong2* A3 = (const ulonglong2*)(sA + (r0 + 3) * HHP);
    const ulonglong2* Bp = (const ulonglong2*)sB4 + lane;
    const ulonglong2* Wp = (const ulonglong2*)sW3;

    u64 acc0 = 0ull, acc1 = 0ull, acc2 = 0ull, acc3 = 0ull;
    #pragma unroll 5
    for (int q = 0; q < NQ; ++q) {
        ulonglong2 a0 = A0[q];
        ulonglong2 a1 = A1[q];
        ulonglong2 a2 = A2[q];
        ulonglong2 a3 = A3[q];
        ulonglong2 w  = Wp[q];
        ulonglong2 bq = Bp[q * 32];

        pd2(a0.x, bq.x, w.x, acc0);
        pd2(a1.x, bq.x, w.x, acc1);
        pd2(a2.x, bq.x, w.x, acc2);
        pd2(a3.x, bq.x, w.x, acc3);

        pd2(a0.y, bq.y, w.y, acc0);
        pd2(a1.y, bq.y, w.y, acc1);
        pd2(a2.y, bq.y, w.y, acc2);
        pd2(a3.y, bq.y, w.y, acc3);
    }

    float2 f0 = unpk(acc0), f1 = unpk(acc1), f2 = unpk(acc2), f3 = unpk(acc3);
    float zs[4] = {f0.x + f0.y, f1.x + f1.y, f2.x + f2.y, f3.x + f3.y};
    #pragma unroll
    for (int t = 0; t < 4; ++t) {
        int i1 = I0 + t;
        if (i1 < i2) {
            float z = zs[t] + b3;
            float s = 1.f / (1.f + __expf(-z));
            int p = i1 * (2 * NN - 1 - i1) / 2 + (i2 - i1 - 1);
            out[b * PP + p] = s;
        }
    }
}

// ---------------------------------------------------------------- launch
extern "C" void kernel_launch(void* const* d_in, const int* in_sizes, int n_in,
                              void* d_out, int out_size) {
    const float* x  = (const float*)d_in[0];
    // d_in[1] = in_hitnr (unused by reference)
    const float* W1 = (const float*)d_in[2];
    const float* b1 = (const float*)d_in[3];
    const float* W2 = (const float*)d_in[4];
    const float* b2 = (const float*)d_in[5];
    const float* W3 = (const float*)d_in[6];
    const float* b3 = (const float*)d_in[7];
    float* out = (float*)d_out;

    k_fold<<<1, 512>>>(W1, b1, W2, b2);
    k_pairs<<<BB * 10, 256>>>(x, W3, b3, out);
}

// round 14
// speedup vs baseline: 1.4962x; 1.0122x over previous
#include <cuda_runtime.h>

#define BB 64
#define NN 128
#define FF 4
#define HH 100
#define HHP 104
#define NQ 25            // HH/4 quads
#define PP 8128          // NN*(NN-1)/2

typedef unsigned long long u64;

// folded weights (written by k_fold, read by k_pairs)
__device__ __align__(16) float g_M1[FF * HHP];
__device__ __align__(16) float g_M2[FF * HHP];
__device__ __align__(16) float g_c2[HHP];

// packed 2-dim pair op: acc += max(a+b, 0) * w   (both f32 halves)
__device__ __forceinline__ void pd2(u64 a, u64 b, u64 w, u64& acc) {
    asm("{\n\t"
        ".reg .b64 t;\n\t"
        ".reg .f32 lo, hi;\n\t"
        "add.rn.f32x2 t, %1, %2;\n\t"
        "mov.b64 {lo, hi}, t;\n\t"
        "max.f32 lo, lo, 0f00000000;\n\t"
        "max.f32 hi, hi, 0f00000000;\n\t"
        "mov.b64 t, {lo, hi};\n\t"
        "fma.rn.f32x2 %0, t, %3, %0;\n\t"
        "}" : "+l"(acc) : "l"(a), "l"(b), "l"(w));
}

__device__ __forceinline__ float2 unpk(u64 t) {
    float2 f;
    asm("mov.b64 {%0, %1}, %2;" : "=f"(f.x), "=f"(f.y) : "l"(t));
    return f;
}

// ---------------------------------------------------------------- K1: fold (one block)
__global__ void __launch_bounds__(512) k_fold(const float* __restrict__ W1,
                                              const float* __restrict__ b1,
                                              const float* __restrict__ W2,
                                              const float* __restrict__ b2) {
    __shared__ float sW1T[HH * 8];        // [k][f] transposed
    __shared__ float sb1[HH];
    __shared__ float sPart[500 * 9];
    const int tid = threadIdx.x;

    for (int i = tid; i < 2 * FF * HH; i += 512) {
        int f = i / HH, k = i % HH;
        sW1T[k * 8 + f] = W1[i];
    }
    if (tid < HH) sb1[tid] = b1[tid];
    __syncthreads();

    if (tid < 500) {
        const int d  = tid % HH;
        const int kc = tid / HH;
        float m[9];
        #pragma unroll
        for (int i = 0; i < 9; ++i) m[i] = 0.f;
        #pragma unroll 5
        for (int kk = 0; kk < 20; ++kk) {
            int k = kc * 20 + kk;
            float w = W2[k * HH + d];
            float4 wa = *(const float4*)(sW1T + k * 8);
            float4 wb = *(const float4*)(sW1T + k * 8 + 4);
            m[0] = fmaf(wa.x, w, m[0]); m[1] = fmaf(wa.y, w, m[1]);
            m[2] = fmaf(wa.z, w, m[2]); m[3] = fmaf(wa.w, w, m[3]);
            m[4] = fmaf(wb.x, w, m[4]); m[5] = fmaf(wb.y, w, m[5]);
            m[6] = fmaf(wb.z, w, m[6]); m[7] = fmaf(wb.w, w, m[7]);
            m[8] = fmaf(sb1[k], w, m[8]);
        }
        #pragma unroll
        for (int i = 0; i < 9; ++i) sPart[tid * 9 + i] = m[i];
    }
    __syncthreads();

    if (tid < HH) {
        float s[9];
        #pragma unroll
        for (int i = 0; i < 9; ++i) s[i] = 0.f;
        #pragma unroll
        for (int kc = 0; kc < 5; ++kc)
            #pragma unroll
            for (int i = 0; i < 9; ++i)
                s[i] += sPart[(kc * HH + tid) * 9 + i];
        #pragma unroll
        for (int f = 0; f < FF; ++f) { g_M1[f * HHP + tid] = s[f]; g_M2[f * HHP + tid] = s[4 + f]; }
        g_c2[tid] = s[8] + b2[tid];
    }
    // make g_* visible, then allow the dependent grid to pass its sync point
    __syncthreads();
    __threadfence();
    cudaTriggerProgrammaticLaunchCompletion();
}

__device__ __forceinline__ int j_of(int g) { return (g < 8) ? 0 : (g < 24) ? 1 : (g < 48) ? 2 : 3; }
__device__ __forceinline__ int i0_of(int g, int j) {
    int base = (j == 0) ? 0 : (j == 1) ? 8 : (j == 2) ? 24 : 48;
    return (g - base) * 4;
}

// ---------------------------------------------------------------- K2: fused transform + pairs
// Block = (batch, blk4): 4 consecutive tiles of the 80-tile list (one strip,
// 16 contiguous A-rows). One 4x32 tile per warp; packed f32x2 inner math.
__global__ void __launch_bounds__(128, 9)
k_pairs(const float* __restrict__ x,
        const float* __restrict__ W3, const float* __restrict__ b3p,
        float* __restrict__ out) {
    __shared__ __align__(16) float  sA[16 * HHP];      // 6656 B
    __shared__ __align__(16) float4 sB4[NQ * 32];      // 12800 B
    __shared__ __align__(16) float  sM1[FF * HHP];
    __shared__ __align__(16) float  sM2[FF * HHP];
    __shared__ __align__(16) float  sc2[HHP];
    __shared__ __align__(16) float  sW3[HHP];

    const int tid  = threadIdx.x;
    const int warp = tid >> 5;
    const int lane = tid & 31;
    const int b    = blockIdx.x / 20;
    const int blk4 = blockIdx.x % 20;

    const int g0     = blk4 * 4;           // first tile of this block
    const int j      = j_of(g0);
    const int J0     = j * 32;
    const int row_lo = i0_of(g0, j);       // 16 contiguous rows start here

    // ---- phase 0 (independent of k_fold): W3 -------------------------------
    if (tid < NQ) *(float4*)(sW3 + tid * 4) = ((const float4*)W3)[tid];

    // wait for k_fold's g_M1/g_M2/g_c2
    cudaGridDependencySynchronize();

    // ---- phase 0b: stage folded weights ------------------------------------
    if (tid < FF * HHP / 4) {
        ((float4*)sM1)[tid] = ((const float4*)g_M1)[tid];
        ((float4*)sM2)[tid] = ((const float4*)g_M2)[tid];
    }
    if (tid >= 102 && tid < 102 + HHP / 4)
        ((float4*)sc2)[tid - 102] = ((const float4*)g_c2)[tid - 102];
    __syncthreads();

    // ---- phase 1a: A rows [row_lo, row_lo+16), c2 folded in ----------------
    for (int it = tid; it < 16 * NQ; it += 128) {
        int r = it / NQ, q = it % NQ, d0 = q * 4;
        float4 xv = *(const float4*)(x + (b * NN + row_lo + r) * FF);
        float4 a  = *(const float4*)(sc2 + d0);
        #pragma unroll
        for (int f = 0; f < FF; ++f) {
            float xf = (f == 0) ? xv.x : (f == 1) ? xv.y : (f == 2) ? xv.z : xv.w;
            float4 m1 = *(const float4*)(sM1 + f * HHP + d0);
            a.x = fmaf(xf, m1.x, a.x); a.y = fmaf(xf, m1.y, a.y);
            a.z = fmaf(xf, m1.z, a.z); a.w = fmaf(xf, m1.w, a.w);
        }
        *(float4*)(sA + r * HHP + d0) = a;
    }
    // ---- phase 1b: B strip cols [J0, J0+32) --------------------------------
    for (int it = tid; it < 32 * NQ; it += 128) {
        int col = it & 31, q = it >> 5, d0 = q * 4;
        float4 xv = *(const float4*)(x + (b * NN + J0 + col) * FF);
        float4 v  = make_float4(0.f, 0.f, 0.f, 0.f);
        #pragma unroll
        for (int f = 0; f < FF; ++f) {
            float xf = (f == 0) ? xv.x : (f == 1) ? xv.y : (f == 2) ? xv.z : xv.w;
            float4 m2 = *(const float4*)(sM2 + f * HHP + d0);
            v.x = fmaf(xf, m2.x, v.x); v.y = fmaf(xf, m2.y, v.y);
            v.z = fmaf(xf, m2.z, v.z); v.w = fmaf(xf, m2.w, v.w);
        }
        sB4[q * 32 + col] = v;
    }
    __syncthreads();

    // ---- phase 2: one 4x32 tile per warp, packed f32x2 math ----------------
    const int r0 = warp * 4;               // local row of tile
    const int I0 = row_lo + r0;
    const int i2 = J0 + lane;
    const float b3 = b3p[0];

    const ulonglong2* A0 = (const ulonglong2*)(sA + (r0 + 0) * HHP);
    const ulonglong2* A1 = (const ulonglong2*)(sA + (r0 + 1) * HHP);
    const ulonglong2* A2 = (const ulonglong2*)(sA + (r0 + 2) * HHP);
    const ulonglong2* A3 = (const ulonglong2*)(sA + (r0 + 3) * HHP);
    const ulonglong2* Bp = (const ulonglong2*)sB4 + lane;
    const ulonglong2* Wp = (const ulonglong2*)sW3;

    u64 acc0 = 0ull, acc1 = 0ull, acc2 = 0ull, acc3 = 0ull;
    #pragma unroll 5
    for (int q = 0; q < NQ; ++q) {
        ulonglong2 a0 = A0[q];
        ulonglong2 a1 = A1[q];
        ulonglong2 a2 = A2[q];
        ulonglong2 a3 = A3[q];
        ulonglong2 w  = Wp[q];
        ulonglong2 bq = Bp[q * 32];

        pd2(a0.x, bq.x, w.x, acc0);
        pd2(a1.x, bq.x, w.x, acc1);
        pd2(a2.x, bq.x, w.x, acc2);
        pd2(a3.x, bq.x, w.x, acc3);

        pd2(a0.y, bq.y, w.y, acc0);
        pd2(a1.y, bq.y, w.y, acc1);
        pd2(a2.y, bq.y, w.y, acc2);
        pd2(a3.y, bq.y, w.y, acc3);
    }

    float2 f0 = unpk(acc0), f1 = unpk(acc1), f2 = unpk(acc2), f3 = unpk(acc3);
    float zs[4] = {f0.x + f0.y, f1.x + f1.y, f2.x + f2.y, f3.x + f3.y};
    #pragma unroll
    for (int t = 0; t < 4; ++t) {
        int i1 = I0 + t;
        if (i1 < i2) {
            float z = zs[t] + b3;
            float s = 1.f / (1.f + __expf(-z));
            int p = i1 * (2 * NN - 1 - i1) / 2 + (i2 - i1 - 1);
            out[b * PP + p] = s;
        }
    }
}

// ---------------------------------------------------------------- launch
extern "C" void kernel_launch(void* const* d_in, const int* in_sizes, int n_in,
                              void* d_out, int out_size) {
    const float* x  = (const float*)d_in[0];
    // d_in[1] = in_hitnr (unused by reference)
    const float* W1 = (const float*)d_in[2];
    const float* b1 = (const float*)d_in[3];
    const float* W2 = (const float*)d_in[4];
    const float* b2 = (const float*)d_in[5];
    const float* W3 = (const float*)d_in[6];
    const float* b3 = (const float*)d_in[7];
    float* out = (float*)d_out;

    k_fold<<<1, 512>>>(W1, b1, W2, b2);

    // k_pairs with programmatic dependent launch (overlaps with k_fold).
    cudaLaunchConfig_t cfg = {};
    cfg.gridDim  = dim3(BB * 20, 1, 1);
    cfg.blockDim = dim3(128, 1, 1);
    cudaLaunchAttribute attr[1];
    attr[0].id = cudaLaunchAttributeProgrammaticStreamSerialization;
    attr[0].val.programmaticStreamSerializationAllowed = 1;
    cfg.attrs = attr;
    cfg.numAttrs = 1;
    cudaError_t err = cudaLaunchKernelEx(&cfg, k_pairs, x, W3, b3, out);
    if (err != cudaSuccess) {
        // fallback: plain stream-ordered launch (gridDependencySynchronize is
        // trivially satisfied when not PDL-launched)
        k_pairs<<<BB * 20, 128>>>(x, W3, b3, out);
    }
}